// round 2
// baseline (speedup 1.0000x reference)
#include <cuda_runtime.h>
#include <cstdint>
#include <cstddef>

// Problem constants
#define BB    32
#define TT    2048
#define FIN   63
#define FDIM  64
#define LUDIM 640
#define NCH   64      // number of t-chunks for the parallel scan (was 16 -> occupancy fix)
#define TC    32      // timesteps per chunk  (NCH*TC == TT)
#define NCHAIN 2048   // B*U chains

// GEMM tiling
#define BT   128      // t rows per block
#define BLU  128      // lu cols per block
#define TPAD 132      // padded t stride for f-major X tile (conflict-free tile fill)

// Scratch (static device globals; allocation-free per harness rules)
__device__ float g_P[(size_t)BB * TT * LUDIM];      // P[b][t][l*64+u], 167.8 MB
__device__ float g_W[(size_t)NCH * 17 * NCHAIN];    // per-chunk affine coefficients, 8.9 MB

// ---------------- f32x2 helpers (Blackwell packed fp32) ----------------
__device__ __forceinline__ void ffma2(unsigned long long &a, unsigned long long x, unsigned long long k) {
    asm("fma.rn.f32x2 %0, %1, %2, %0;" : "+l"(a) : "l"(x), "l"(k));
}
__device__ __forceinline__ float2 unpack2(unsigned long long v) {
    float2 r;
    asm("mov.b64 {%0,%1}, %2;" : "=f"(r.x), "=f"(r.y) : "l"(v));
    return r;
}

// ---------------- Kernel 1: P = X @ K  (X = [x | time]) ----------------
// Grid: (TT/BT, LUDIM/BLU, BB). Block: 256 threads (tx=tid&15 over lu, ty=tid>>4 over t).
// Thread tile: 8 t-rows x 8 lu-cols. f32x2 lanes are (t, t+1) pairs:
//   - X operand: packed pair of consecutive t values, direct LDS from f-major tile.
//   - K operand: pre-DUPLICATED (k,k) float2 in smem, direct LDS.128 -> two operands.
// Zero splat MOVs in the inner loop.
extern "C" __global__ void __launch_bounds__(256, 2)
lrsig_gemm(const float* __restrict__ x, const float* __restrict__ kern)
{
    extern __shared__ float smem[];
    float*  sX  = smem;                       // [f][TPAD] floats (f-major)
    float2* sK2 = (float2*)(smem + FDIM * TPAD);  // [f][BLU] duplicated (k,k)

    const int tid = threadIdx.x;
    const int tx  = tid & 15;
    const int ty  = tid >> 4;
    const int t0  = blockIdx.x * BT;
    const int lu0 = blockIdx.y * BLU;
    const int b   = blockIdx.z;

    // Load X tile (coalesced over f), store f-major (transposed), padded stride.
    // f == 63 is the synthetic time feature: t*(2/(T-1)) - 1.
    for (int e = tid; e < BT * FDIM; e += 256) {
        int f  = e & 63;
        int tl = e >> 6;
        int t  = t0 + tl;
        float v;
        if (f < FIN) v = x[((size_t)b * TT + t) * FIN + f];
        else         v = (float)t * (2.0f / 2047.0f) - 1.0f;
        sX[f * TPAD + tl] = v;
    }
    // Load K tile duplicated: sK2[f*BLU + j] = (k, k), k = kern[f][lu0+j]
    for (int e = tid; e < FDIM * BLU; e += 256) {
        int f = e >> 7;
        int j = e & 127;
        float v = kern[f * LUDIM + lu0 + j];
        sK2[e] = make_float2(v, v);
    }
    __syncthreads();

    // acc[tp][j]: t-pair tp (t = ty*8 + 2*tp, +1), lu col j (lu = lu0 + tx*8 + j)
    unsigned long long acc[4][8];
#pragma unroll
    for (int tp = 0; tp < 4; tp++)
#pragma unroll
        for (int j = 0; j < 8; j++) acc[tp][j] = 0ULL;

    const ulonglong2* Xu = reinterpret_cast<const ulonglong2*>(sX);   // 132 fl = 33 u2/row
    const ulonglong2* Ku = reinterpret_cast<const ulonglong2*>(sK2);  // 128 f2 = 64 u2/row

#pragma unroll 8
    for (int f = 0; f < FDIM; f++) {
        // 8 t values = 4 packed pairs, two LDS.128
        ulonglong2 xa = Xu[f * 33 + ty * 2];      // pairs (t0..t1),(t2..t3)
        ulonglong2 xb = Xu[f * 33 + ty * 2 + 1];  // pairs (t4..t5),(t6..t7)
        // 8 duplicated K values = 4 LDS.128 (each .x/.y is one (k,k) operand)
        ulonglong2 k0 = Ku[f * 64 + tx * 4 + 0];
        ulonglong2 k1 = Ku[f * 64 + tx * 4 + 1];
        ulonglong2 k2 = Ku[f * 64 + tx * 4 + 2];
        ulonglong2 k3 = Ku[f * 64 + tx * 4 + 3];

        unsigned long long xp[4] = { xa.x, xa.y, xb.x, xb.y };
        unsigned long long kd[8] = { k0.x, k0.y, k1.x, k1.y, k2.x, k2.y, k3.x, k3.y };
#pragma unroll
        for (int tp = 0; tp < 4; tp++)
#pragma unroll
            for (int j = 0; j < 8; j++)
                ffma2(acc[tp][j], xp[tp], kd[j]);
    }

    // Write P[b][t][lu0 + tx*8 + ...]: per t-pair, two rows, 2x float4 each.
#pragma unroll
    for (int tp = 0; tp < 4; tp++) {
        float lo[8], hi[8];
#pragma unroll
        for (int j = 0; j < 8; j++) {
            float2 v = unpack2(acc[tp][j]);
            lo[j] = v.x; hi[j] = v.y;
        }
        int t = t0 + ty * 8 + 2 * tp;
        float* op0 = g_P + ((size_t)b * TT + t    ) * LUDIM + lu0 + tx * 8;
        float* op1 = g_P + ((size_t)b * TT + t + 1) * LUDIM + lu0 + tx * 8;
        reinterpret_cast<float4*>(op0)[0] = make_float4(lo[0], lo[1], lo[2], lo[3]);
        reinterpret_cast<float4*>(op0)[1] = make_float4(lo[4], lo[5], lo[6], lo[7]);
        reinterpret_cast<float4*>(op1)[0] = make_float4(hi[0], hi[1], hi[2], hi[3]);
        reinterpret_cast<float4*>(op1)[1] = make_float4(hi[4], hi[5], hi[6], hi[7]);
    }
}

// ---------------- Kernel 2: per-chunk scan coefficients ----------------
// One thread per (chain, chunk). Computes the 17 affine coefficients of this
// chunk's action on the signature state (Chen identity / chunked scan).
extern "C" __global__ void __launch_bounds__(256)
lrsig_scan(void)
{
    const int c     = blockIdx.x;
    const int chain = blockIdx.y * 256 + threadIdx.x;
    const int b = chain >> 6;
    const int u = chain & 63;

    const float* base = g_P + (size_t)b * TT * LUDIM + u;
    const int t0 = c * TC;
    const int tp = (c == 0) ? 0 : (t0 - 1);

    float prev[10];
#pragma unroll
    for (int l = 0; l < 10; l++) prev[l] = base[(size_t)tp * LUDIM + l * 64];

    float e1=0.f,e3=0.f,e4=0.f,e43=0.f,e6=0.f,e7=0.f,e76=0.f,e8=0.f,e87=0.f,e876=0.f;
    float S2=0.f,S5=0.f,S9=0.f,W21=0.f,W54=0.f,W543=0.f,W98=0.f,W987=0.f,W9876=0.f,y0=0.f;

#pragma unroll 4
    for (int i = 0; i < TC; i++) {
        const float* p = base + (size_t)(t0 + i) * LUDIM;
        float m[10];
#pragma unroll
        for (int l = 0; l < 10; l++) {
            float v = p[l * 64];
            m[l] = v - prev[l];
            prev[l] = v;
        }
        // All RHS below use pre-update (exclusive) values.
        y0   += m[0];
        W21   = fmaf(m[2], e1,   W21);   S2 += m[2];
        W54   = fmaf(m[5], e4,   W54);
        W543  = fmaf(m[5], e43,  W543);  S5 += m[5];
        W98   = fmaf(m[9], e8,   W98);
        W987  = fmaf(m[9], e87,  W987);
        W9876 = fmaf(m[9], e876, W9876); S9 += m[9];
        e43   = fmaf(m[4], e3,   e43);
        e876  = fmaf(m[8], e76,  e876);
        e87   = fmaf(m[8], e7,   e87);
        e76   = fmaf(m[7], e6,   e76);
        e1 += m[1]; e3 += m[3]; e4 += m[4];
        e6 += m[6]; e7 += m[7]; e8 += m[8];
    }

    float* w = g_W + (size_t)c * 17 * NCHAIN + chain;
    w[ 0 * NCHAIN] = y0 + W21 + W543 + W9876;  // state-independent Y contribution
    w[ 1 * NCHAIN] = S2;   w[ 2 * NCHAIN] = S5;   w[ 3 * NCHAIN] = S9;
    w[ 4 * NCHAIN] = W54;  w[ 5 * NCHAIN] = W98;  w[ 6 * NCHAIN] = W987;
    w[ 7 * NCHAIN] = e1;   w[ 8 * NCHAIN] = e3;   w[ 9 * NCHAIN] = e4;
    w[10 * NCHAIN] = e43;  w[11 * NCHAIN] = e6;   w[12 * NCHAIN] = e7;
    w[13 * NCHAIN] = e76;  w[14 * NCHAIN] = e8;   w[15 * NCHAIN] = e87;
    w[16 * NCHAIN] = e876;
}

// ---------------- Kernel 3: fold chunks per chain ----------------
extern "C" __global__ void __launch_bounds__(256)
lrsig_combine(float* __restrict__ out)
{
    const int chain = blockIdx.x * 256 + threadIdx.x;
    float y = 0.f, s1 = 0.f, s3 = 0.f, sa = 0.f, s6 = 0.f, sb = 0.f, sc = 0.f;

    for (int c = 0; c < NCH; c++) {
        const float* w = g_W + (size_t)c * 17 * NCHAIN + chain;
        float Y0   = w[ 0 * NCHAIN];
        float S2   = w[ 1 * NCHAIN], S5  = w[ 2 * NCHAIN], S9  = w[ 3 * NCHAIN];
        float W54  = w[ 4 * NCHAIN], W98 = w[ 5 * NCHAIN], W987= w[ 6 * NCHAIN];
        float E1   = w[ 7 * NCHAIN], E3  = w[ 8 * NCHAIN], E4  = w[ 9 * NCHAIN];
        float E43  = w[10 * NCHAIN], E6  = w[11 * NCHAIN], E7  = w[12 * NCHAIN];
        float E76  = w[13 * NCHAIN], E8  = w[14 * NCHAIN], E87 = w[15 * NCHAIN];
        float E876 = w[16 * NCHAIN];

        // Y contribution uses pre-chunk state
        y += Y0 + s1 * S2 + sa * S5 + s3 * W54 + sc * S9 + sb * W98 + s6 * W987;
        // State transition (note update order: sc/sb/sa use pre-update partners)
        sc += sb * E8 + s6 * E87 + E876;
        sb += s6 * E7 + E76;
        sa += s3 * E4 + E43;
        s1 += E1; s3 += E3; s6 += E6;
    }
    out[chain] = y;   // out[b*64 + u] == Y[b][u]
}

// ---------------- Launch ----------------
extern "C" void kernel_launch(void* const* d_in, const int* in_sizes, int n_in,
                              void* d_out, int out_size)
{
    const float* x    = (const float*)d_in[0];  // (32, 2048, 63) f32
    const float* kern = (const float*)d_in[1];  // (64, 10, 64)  f32

    const size_t smem_bytes = (size_t)FDIM * TPAD * sizeof(float)
                            + (size_t)FDIM * BLU * sizeof(float2); // 33,792 + 65,536 = 99,328 B
    cudaFuncSetAttribute(lrsig_gemm, cudaFuncAttributeMaxDynamicSharedMemorySize,
                         (int)smem_bytes);

    lrsig_gemm<<<dim3(TT / BT, LUDIM / BLU, BB), 256, smem_bytes>>>(x, kern);
    lrsig_scan<<<dim3(NCH, NCHAIN / 256), 256>>>();
    lrsig_combine<<<NCHAIN / 256, 256>>>((float*)d_out);
}

// round 3
// speedup vs baseline: 1.9569x; 1.9569x over previous
#include <cuda_runtime.h>
#include <cstdint>
#include <cstddef>

// Problem constants
#define BB    32
#define TT    2048
#define FIN   63
#define FDIM  64
#define LUDIM 640
#define NCH   64      // number of t-chunks for the parallel scan
#define TC    32      // timesteps per chunk  (NCH*TC == TT)
#define NCHAIN 2048   // B*U chains

// GEMM tiling
#define BT   128      // t rows per block
#define BLU  128      // lu cols per block
#define TPAD 132      // padded t stride for f-major X tile

// Scratch (static device globals; allocation-free per harness rules)
__device__ float g_P[(size_t)BB * TT * LUDIM];      // P[b][t][l*64+u], 167.8 MB
__device__ float g_W[(size_t)NCH * 17 * NCHAIN];    // per-chunk affine coefficients, 8.9 MB

// ---------------- f32x2 helpers (Blackwell packed fp32) ----------------
__device__ __forceinline__ void ffma2(unsigned long long &a, unsigned long long x, unsigned long long k) {
    asm("fma.rn.f32x2 %0, %1, %2, %0;" : "+l"(a) : "l"(x), "l"(k));
}
__device__ __forceinline__ float2 unpack2(unsigned long long v) {
    float2 r;
    asm("mov.b64 {%0,%1}, %2;" : "=f"(r.x), "=f"(r.y) : "l"(v));
    return r;
}

// ---------------- Kernel 1: P = X @ K  (X = [x | time]) ----------------
// Grid: (TT/BT, LUDIM/BLU, BB). Block: 256 threads (tx=tid&15, ty=tid>>4).
// Thread tile: 8 t-rows x 8 lu-cols. f32x2 lanes are (t, t+1) pairs:
//   - X operand: packed (t,t+1) pair, broadcast LDS.128 from f-major tile.
//   - K operand: pre-DUPLICATED (k,k) pairs; each of the 4 K reads is a
//     contiguous 16B-stride LDS.128 across tx -> conflict-free (round-2's
//     64B-stride pattern caused 8-way conflicts).
// Thread's columns: lu = lu0 + 32*c + 2*tx + k, c=0..3, k=0..1.
extern "C" __global__ void __launch_bounds__(256, 2)
lrsig_gemm(const float* __restrict__ x, const float* __restrict__ kern)
{
    extern __shared__ float smem[];
    float*  sX  = smem;                           // [f][TPAD] floats (f-major)
    float2* sKd = (float2*)(smem + FDIM * TPAD);  // [f][BLU] duplicated (k,k)

    const int tid = threadIdx.x;
    const int tx  = tid & 15;
    const int ty  = tid >> 4;
    const int t0  = blockIdx.x * BT;
    const int lu0 = blockIdx.y * BLU;
    const int b   = blockIdx.z;

    // Load X tile (gmem-coalesced over f), store f-major (transposed), padded.
    // f == 63 is the synthetic time feature: t*(2/(T-1)) - 1.
    for (int e = tid; e < BT * FDIM; e += 256) {
        int f  = e & 63;
        int tl = e >> 6;
        int t  = t0 + tl;
        float v;
        if (f < FIN) v = x[((size_t)b * TT + t) * FIN + f];
        else         v = (float)t * (2.0f / 2047.0f) - 1.0f;
        sX[f * TPAD + tl] = v;
    }
    // Load K tile duplicated: sKd[f*BLU + j] = (k, k), k = kern[f][lu0+j]
    for (int e = tid; e < FDIM * BLU; e += 256) {
        int f = e >> 7;
        int j = e & 127;
        float v = kern[f * LUDIM + lu0 + j];
        sKd[e] = make_float2(v, v);
    }
    __syncthreads();

    // acc[tp][c][k]: t-pair tp (t = t0 + ty*8 + 2*tp), col 32*c + 2*tx + k
    unsigned long long acc[4][4][2];
#pragma unroll
    for (int tp = 0; tp < 4; tp++)
#pragma unroll
        for (int c = 0; c < 4; c++) { acc[tp][c][0] = 0ULL; acc[tp][c][1] = 0ULL; }

    const ulonglong2* Xu = reinterpret_cast<const ulonglong2*>(sX);   // 33 u2/row
    const ulonglong2* Kd = reinterpret_cast<const ulonglong2*>(sKd);  // 64 u2/row

#pragma unroll 8
    for (int f = 0; f < FDIM; f++) {
        // 8 t values = 4 packed (t,t+1) pairs; 2 broadcast LDS.128
        ulonglong2 xa = Xu[f * 33 + ty * 2];
        ulonglong2 xb = Xu[f * 33 + ty * 2 + 1];
        unsigned long long xp[4] = { xa.x, xa.y, xb.x, xb.y };
        // 4 conflict-free LDS.128: read c covers dup cols (32c+2tx, 32c+2tx+1)
        ulonglong2 kc[4];
#pragma unroll
        for (int c = 0; c < 4; c++) kc[c] = Kd[f * 64 + c * 16 + tx];
#pragma unroll
        for (int tp = 0; tp < 4; tp++)
#pragma unroll
            for (int c = 0; c < 4; c++) {
                ffma2(acc[tp][c][0], xp[tp], kc[c].x);
                ffma2(acc[tp][c][1], xp[tp], kc[c].y);
            }
    }

    // Write P: per t-pair, two rows; 4 float2 stores per row (coalesced: tx
    // consecutive -> 8B stride -> 128B segments).
#pragma unroll
    for (int tp = 0; tp < 4; tp++) {
        int t = t0 + ty * 8 + 2 * tp;
        float* op0 = g_P + ((size_t)b * TT + t    ) * LUDIM + lu0 + 2 * tx;
        float* op1 = g_P + ((size_t)b * TT + t + 1) * LUDIM + lu0 + 2 * tx;
#pragma unroll
        for (int c = 0; c < 4; c++) {
            float2 v0 = unpack2(acc[tp][c][0]);
            float2 v1 = unpack2(acc[tp][c][1]);
            reinterpret_cast<float2*>(op0 + 32 * c)[0] = make_float2(v0.x, v1.x);
            reinterpret_cast<float2*>(op1 + 32 * c)[0] = make_float2(v0.y, v1.y);
        }
    }
}

// ---------------- Kernel 2: per-chunk scan coefficients ----------------
// One thread per (chain, chunk). Computes the 17 affine coefficients of this
// chunk's action on the signature state (Chen identity / chunked scan).
extern "C" __global__ void __launch_bounds__(256)
lrsig_scan(void)
{
    const int c     = blockIdx.x;
    const int chain = blockIdx.y * 256 + threadIdx.x;
    const int b = chain >> 6;
    const int u = chain & 63;

    const float* base = g_P + (size_t)b * TT * LUDIM + u;
    const int t0 = c * TC;
    const int tp = (c == 0) ? 0 : (t0 - 1);

    float prev[10];
#pragma unroll
    for (int l = 0; l < 10; l++) prev[l] = base[(size_t)tp * LUDIM + l * 64];

    float e1=0.f,e3=0.f,e4=0.f,e43=0.f,e6=0.f,e7=0.f,e76=0.f,e8=0.f,e87=0.f,e876=0.f;
    float S2=0.f,S5=0.f,S9=0.f,W21=0.f,W54=0.f,W543=0.f,W98=0.f,W987=0.f,W9876=0.f,y0=0.f;

#pragma unroll 4
    for (int i = 0; i < TC; i++) {
        const float* p = base + (size_t)(t0 + i) * LUDIM;
        float m[10];
#pragma unroll
        for (int l = 0; l < 10; l++) {
            float v = p[l * 64];
            m[l] = v - prev[l];
            prev[l] = v;
        }
        // All RHS below use pre-update (exclusive) values.
        y0   += m[0];
        W21   = fmaf(m[2], e1,   W21);   S2 += m[2];
        W54   = fmaf(m[5], e4,   W54);
        W543  = fmaf(m[5], e43,  W543);  S5 += m[5];
        W98   = fmaf(m[9], e8,   W98);
        W987  = fmaf(m[9], e87,  W987);
        W9876 = fmaf(m[9], e876, W9876); S9 += m[9];
        e43   = fmaf(m[4], e3,   e43);
        e876  = fmaf(m[8], e76,  e876);
        e87   = fmaf(m[8], e7,   e87);
        e76   = fmaf(m[7], e6,   e76);
        e1 += m[1]; e3 += m[3]; e4 += m[4];
        e6 += m[6]; e7 += m[7]; e8 += m[8];
    }

    float* w = g_W + (size_t)c * 17 * NCHAIN + chain;
    w[ 0 * NCHAIN] = y0 + W21 + W543 + W9876;  // state-independent Y contribution
    w[ 1 * NCHAIN] = S2;   w[ 2 * NCHAIN] = S5;   w[ 3 * NCHAIN] = S9;
    w[ 4 * NCHAIN] = W54;  w[ 5 * NCHAIN] = W98;  w[ 6 * NCHAIN] = W987;
    w[ 7 * NCHAIN] = e1;   w[ 8 * NCHAIN] = e3;   w[ 9 * NCHAIN] = e4;
    w[10 * NCHAIN] = e43;  w[11 * NCHAIN] = e6;   w[12 * NCHAIN] = e7;
    w[13 * NCHAIN] = e76;  w[14 * NCHAIN] = e8;   w[15 * NCHAIN] = e87;
    w[16 * NCHAIN] = e876;
}

// ---------------- Kernel 3: fold chunks per chain ----------------
extern "C" __global__ void __launch_bounds__(256)
lrsig_combine(float* __restrict__ out)
{
    const int chain = blockIdx.x * 256 + threadIdx.x;
    float y = 0.f, s1 = 0.f, s3 = 0.f, sa = 0.f, s6 = 0.f, sb = 0.f, sc = 0.f;

    for (int c = 0; c < NCH; c++) {
        const float* w = g_W + (size_t)c * 17 * NCHAIN + chain;
        float Y0   = w[ 0 * NCHAIN];
        float S2   = w[ 1 * NCHAIN], S5  = w[ 2 * NCHAIN], S9  = w[ 3 * NCHAIN];
        float W54  = w[ 4 * NCHAIN], W98 = w[ 5 * NCHAIN], W987= w[ 6 * NCHAIN];
        float E1   = w[ 7 * NCHAIN], E3  = w[ 8 * NCHAIN], E4  = w[ 9 * NCHAIN];
        float E43  = w[10 * NCHAIN], E6  = w[11 * NCHAIN], E7  = w[12 * NCHAIN];
        float E76  = w[13 * NCHAIN], E8  = w[14 * NCHAIN], E87 = w[15 * NCHAIN];
        float E876 = w[16 * NCHAIN];

        // Y contribution uses pre-chunk state
        y += Y0 + s1 * S2 + sa * S5 + s3 * W54 + sc * S9 + sb * W98 + s6 * W987;
        // State transition (sc/sb/sa use pre-update partners)
        sc += sb * E8 + s6 * E87 + E876;
        sb += s6 * E7 + E76;
        sa += s3 * E4 + E43;
        s1 += E1; s3 += E3; s6 += E6;
    }
    out[chain] = y;   // out[b*64 + u] == Y[b][u]
}

// ---------------- Launch ----------------
extern "C" void kernel_launch(void* const* d_in, const int* in_sizes, int n_in,
                              void* d_out, int out_size)
{
    const float* x    = (const float*)d_in[0];  // (32, 2048, 63) f32
    const float* kern = (const float*)d_in[1];  // (64, 10, 64)  f32

    const size_t smem_bytes = (size_t)FDIM * TPAD * sizeof(float)
                            + (size_t)FDIM * BLU * sizeof(float2); // 99,328 B
    cudaFuncSetAttribute(lrsig_gemm, cudaFuncAttributeMaxDynamicSharedMemorySize,
                         (int)smem_bytes);

    lrsig_gemm<<<dim3(TT / BT, LUDIM / BLU, BB), 256, smem_bytes>>>(x, kern);
    lrsig_scan<<<dim3(NCH, NCHAIN / 256), 256>>>();
    lrsig_combine<<<NCHAIN / 256, 256>>>((float*)d_out);
}